// round 1
// baseline (speedup 1.0000x reference)
#include <cuda_runtime.h>

#define B_SZ   512
#define F_SZ   512
#define NK     50
#define DK     16
#define NCOL   (NK*DK)     // 800
#define OUTW   (F_SZ + NK) // 562

// Scratch for the activation matrix (512 x 800 fp32 = 1.6 MB)
__device__ float g_act[B_SZ * NCOL];

// ---------------------------------------------------------------------------
// GEMM: act[m][n] = sum_k x[m][k] * W[k][n]    (512x512 @ 512x800)
// 64x64 tile per block, 256 threads, 4x4 micro-tile, K-step 16.
// ---------------------------------------------------------------------------
__global__ __launch_bounds__(256) void gemm_kernel(const float* __restrict__ A,
                                                   const float* __restrict__ Bm) {
    __shared__ float As[16][64];   // As[k][m]
    __shared__ float Bs[16][64];   // Bs[k][n]

    const int tid = threadIdx.x;
    const int m0  = blockIdx.y * 64;
    const int n0  = blockIdx.x * 64;
    const int ty  = tid >> 4;      // 0..15  (row group)
    const int tx  = tid & 15;      // 0..15  (col group)

    float acc[4][4] = {};

    for (int k0 = 0; k0 < F_SZ; k0 += 16) {
        // Load A tile: 64 rows x 16 k  (store transposed As[k][m])
        #pragma unroll
        for (int p = 0; p < 4; p++) {
            int e = tid + p * 256;
            int r = e >> 4, c = e & 15;
            As[c][r] = A[(m0 + r) * F_SZ + (k0 + c)];
        }
        // Load B tile: 16 k x 64 n
        #pragma unroll
        for (int p = 0; p < 4; p++) {
            int e = tid + p * 256;
            int r = e >> 6, c = e & 63;
            int n = n0 + c;
            Bs[r][c] = (n < NCOL) ? Bm[(k0 + r) * NCOL + n] : 0.0f;
        }
        __syncthreads();

        #pragma unroll
        for (int kk = 0; kk < 16; kk++) {
            float a[4], b[4];
            #pragma unroll
            for (int i = 0; i < 4; i++) a[i] = As[kk][ty * 4 + i];
            #pragma unroll
            for (int j = 0; j < 4; j++) b[j] = Bs[kk][tx * 4 + j];
            #pragma unroll
            for (int i = 0; i < 4; i++)
                #pragma unroll
                for (int j = 0; j < 4; j++)
                    acc[i][j] += a[i] * b[j];
        }
        __syncthreads();
    }

    #pragma unroll
    for (int i = 0; i < 4; i++) {
        int m = m0 + ty * 4 + i;
        #pragma unroll
        for (int j = 0; j < 4; j++) {
            int n = n0 + tx * 4 + j;
            if (n < NCOL) g_act[m * NCOL + n] = acc[i][j];
        }
    }
}

// ---------------------------------------------------------------------------
// Copy x into out[:, 0:512]  (out row stride 562; b*562*4 bytes is 8B aligned
// for every b, so float2 is always safe)
// ---------------------------------------------------------------------------
__global__ __launch_bounds__(256) void copyx_kernel(const float* __restrict__ x,
                                                    float* __restrict__ out) {
    int idx = blockIdx.x * 256 + threadIdx.x;   // 512 * 256 float2 elements
    int b = idx >> 8, j = idx & 255;
    ((float2*)(out + (size_t)b * OUTW))[j] = ((const float2*)(x + (size_t)b * F_SZ))[j];
}

// ---------------------------------------------------------------------------
// Pairwise: features[b,k] = sum_{b2} exp(-sum_d |act[b,k,d]-act[b2,k,d]|)
// grid = (4 b-tiles of 128, 50 k), block = 128 threads, one thread per b.
// act[:,k,:] (32 KB) staged in smem; each thread's own row held in registers.
// ---------------------------------------------------------------------------
__global__ __launch_bounds__(128) void pairwise_kernel(float* __restrict__ out) {
    __shared__ float4 s[B_SZ * 4];   // 512 rows x 16 floats = 32 KB

    const int k   = blockIdx.y;
    const int tid = threadIdx.x;

    // Stage act[:, k, :] : 2048 float4 loads, 16 per thread, coalesced-ish
    for (int i = tid; i < B_SZ * 4; i += 128) {
        int b2 = i >> 2, j = i & 3;
        s[i] = *((const float4*)(g_act + b2 * NCOL + k * DK) + j);
    }
    __syncthreads();

    const int b = blockIdx.x * 128 + tid;
    const float4 a0 = s[b * 4 + 0];
    const float4 a1 = s[b * 4 + 1];
    const float4 a2 = s[b * 4 + 2];
    const float4 a3 = s[b * 4 + 3];

    float sum = 0.0f;
    #pragma unroll 4
    for (int b2 = 0; b2 < B_SZ; b2++) {
        // broadcast reads: all lanes hit the same smem address -> conflict-free
        float4 v0 = s[b2 * 4 + 0];
        float4 v1 = s[b2 * 4 + 1];
        float4 v2 = s[b2 * 4 + 2];
        float4 v3 = s[b2 * 4 + 3];
        // 4 independent partial accumulators for ILP (lat-4 FADD chain)
        float p0 = fabsf(a0.x - v0.x) + fabsf(a0.y - v0.y)
                 + fabsf(a0.z - v0.z) + fabsf(a0.w - v0.w);
        float p1 = fabsf(a1.x - v1.x) + fabsf(a1.y - v1.y)
                 + fabsf(a1.z - v1.z) + fabsf(a1.w - v1.w);
        float p2 = fabsf(a2.x - v2.x) + fabsf(a2.y - v2.y)
                 + fabsf(a2.z - v2.z) + fabsf(a2.w - v2.w);
        float p3 = fabsf(a3.x - v3.x) + fabsf(a3.y - v3.y)
                 + fabsf(a3.z - v3.z) + fabsf(a3.w - v3.w);
        sum += __expf(-((p0 + p1) + (p2 + p3)));
    }

    out[(size_t)b * OUTW + F_SZ + k] = sum;
}

// ---------------------------------------------------------------------------
extern "C" void kernel_launch(void* const* d_in, const int* in_sizes, int n_in,
                              void* d_out, int out_size) {
    const float* x = (const float*)d_in[0];
    const float* W = (const float*)d_in[1];
    float* out = (float*)d_out;

    dim3 gemm_grid((NCOL + 63) / 64, B_SZ / 64);   // 13 x 8
    gemm_kernel<<<gemm_grid, 256>>>(x, W);

    copyx_kernel<<<512, 256>>>(x, out);

    dim3 pw_grid(B_SZ / 128, NK);                  // 4 x 50
    pairwise_kernel<<<pw_grid, 128>>>(out);
}

// round 2
// speedup vs baseline: 1.0712x; 1.0712x over previous
#include <cuda_runtime.h>

#define B_SZ   512
#define F_SZ   512
#define NK     50
#define DK     16
#define NCOL   (NK*DK)     // 800
#define OUTW   (F_SZ + NK) // 562
#define KSPLIT 4
#define KCHUNK (F_SZ / KSPLIT)   // 128
#define ACT_SZ (B_SZ * NCOL)

// 4 partial activation matrices (split-K partials), 4 x 1.6 MB
__device__ float g_act_part[KSPLIT * ACT_SZ];

// ---------------------------------------------------------------------------
// packed f32x2 helpers (Blackwell)
// ---------------------------------------------------------------------------
__device__ __forceinline__ unsigned long long fadd2(unsigned long long x,
                                                    unsigned long long y) {
    unsigned long long r;
    asm("add.rn.f32x2 %0, %1, %2;" : "=l"(r) : "l"(x), "l"(y));
    return r;
}

// ---------------------------------------------------------------------------
// GEMM split-K: act_part[kc][m][n] = sum_{k in chunk kc} x[m][k] * W[k][n]
// 64x64 tile, 256 threads, 4x4 micro-tile, grid (13, 8, 4).
// ---------------------------------------------------------------------------
__global__ __launch_bounds__(256) void gemm_kernel(const float* __restrict__ A,
                                                   const float* __restrict__ Bm) {
    __shared__ float As[16][64];   // As[k][m]
    __shared__ float Bs[16][64];   // Bs[k][n]

    const int tid = threadIdx.x;
    const int m0  = blockIdx.y * 64;
    const int n0  = blockIdx.x * 64;
    const int kc  = blockIdx.z;
    float* out = g_act_part + kc * ACT_SZ;

    const int ty  = tid >> 4;      // 0..15
    const int tx  = tid & 15;      // 0..15

    float acc[4][4] = {};

    const int kbeg = kc * KCHUNK;
    for (int k0 = kbeg; k0 < kbeg + KCHUNK; k0 += 16) {
        #pragma unroll
        for (int p = 0; p < 4; p++) {
            int e = tid + p * 256;
            int r = e >> 4, c = e & 15;
            As[c][r] = A[(m0 + r) * F_SZ + (k0 + c)];
        }
        #pragma unroll
        for (int p = 0; p < 4; p++) {
            int e = tid + p * 256;
            int r = e >> 6, c = e & 63;
            int n = n0 + c;
            Bs[r][c] = (n < NCOL) ? Bm[(k0 + r) * NCOL + n] : 0.0f;
        }
        __syncthreads();

        #pragma unroll
        for (int kk = 0; kk < 16; kk++) {
            float a[4], b[4];
            #pragma unroll
            for (int i = 0; i < 4; i++) a[i] = As[kk][ty * 4 + i];
            #pragma unroll
            for (int j = 0; j < 4; j++) b[j] = Bs[kk][tx * 4 + j];
            #pragma unroll
            for (int i = 0; i < 4; i++)
                #pragma unroll
                for (int j = 0; j < 4; j++)
                    acc[i][j] += a[i] * b[j];
        }
        __syncthreads();
    }

    #pragma unroll
    for (int i = 0; i < 4; i++) {
        int m = m0 + ty * 4 + i;
        #pragma unroll
        for (int j = 0; j < 4; j++) {
            int n = n0 + tx * 4 + j;
            if (n < NCOL) out[m * NCOL + n] = acc[i][j];
        }
    }
}

// ---------------------------------------------------------------------------
// Copy x into out[:, 0:512]
// ---------------------------------------------------------------------------
__global__ __launch_bounds__(256) void copyx_kernel(const float* __restrict__ x,
                                                    float* __restrict__ out) {
    int idx = blockIdx.x * 256 + threadIdx.x;
    int b = idx >> 8, j = idx & 255;
    ((float2*)(out + (size_t)b * OUTW))[j] = ((const float2*)(x + (size_t)b * F_SZ))[j];
}

// ---------------------------------------------------------------------------
// Pairwise: features[b,k] = sum_{b2} exp(-sum_d |act[b,k,d]-act[b2,k,d]|)
// grid = (4 b-tiles of 128, 50 k), block = 128. Stages act[:,k,:] (summing
// the 4 split-K partials) into 32 KB smem, then a packed-f32x2 inner loop.
// ---------------------------------------------------------------------------
__global__ __launch_bounds__(128) void pairwise_kernel(float* __restrict__ out) {
    __shared__ float4 s[B_SZ * 4];   // 512 rows x 16 floats = 32 KB

    const int k   = blockIdx.y;
    const int tid = threadIdx.x;

    const float4* P0 = (const float4*)(g_act_part + 0 * ACT_SZ);
    const float4* P1 = (const float4*)(g_act_part + 1 * ACT_SZ);
    const float4* P2 = (const float4*)(g_act_part + 2 * ACT_SZ);
    const float4* P3 = (const float4*)(g_act_part + 3 * ACT_SZ);

    // Stage act[:, k, :] = sum of the 4 split-K partials
    for (int i = tid; i < B_SZ * 4; i += 128) {
        int b2 = i >> 2, j = i & 3;
        int off = (b2 * NCOL + k * DK) / 4 + j;   // float4 index
        float4 v0 = P0[off], v1 = P1[off], v2 = P2[off], v3 = P3[off];
        float4 r;
        r.x = (v0.x + v1.x) + (v2.x + v3.x);
        r.y = (v0.y + v1.y) + (v2.y + v3.y);
        r.z = (v0.z + v1.z) + (v2.z + v3.z);
        r.w = (v0.w + v1.w) + (v2.w + v3.w);
        s[i] = r;
    }
    __syncthreads();

    const int b = blockIdx.x * 128 + tid;

    // Own row, packed as 8 x f32x2, pre-NEGATED (|v - a| == |a - v|)
    const ulonglong2* sv = (const ulonglong2*)s;
    unsigned long long an[8];
    #pragma unroll
    for (int q = 0; q < 4; q++) {
        ulonglong2 t = sv[b * 4 + q];
        an[2*q]   = t.x ^ 0x8000000080000000ULL;
        an[2*q+1] = t.y ^ 0x8000000080000000ULL;
    }

    const unsigned long long ABSM = 0x7FFFFFFF7FFFFFFFULL;
    float sum = 0.0f;

    #pragma unroll 4
    for (int b2 = 0; b2 < B_SZ; b2++) {
        // broadcast smem reads (conflict-free)
        ulonglong2 v0 = sv[b2 * 4 + 0];
        ulonglong2 v1 = sv[b2 * 4 + 1];
        ulonglong2 v2 = sv[b2 * 4 + 2];
        ulonglong2 v3 = sv[b2 * 4 + 3];

        unsigned long long d0 = fadd2(v0.x, an[0]) & ABSM;
        unsigned long long d1 = fadd2(v0.y, an[1]) & ABSM;
        unsigned long long d2 = fadd2(v1.x, an[2]) & ABSM;
        unsigned long long d3 = fadd2(v1.y, an[3]) & ABSM;
        unsigned long long d4 = fadd2(v2.x, an[4]) & ABSM;
        unsigned long long d5 = fadd2(v2.y, an[5]) & ABSM;
        unsigned long long d6 = fadd2(v3.x, an[6]) & ABSM;
        unsigned long long d7 = fadd2(v3.y, an[7]) & ABSM;

        unsigned long long t0 = fadd2(d0, d1);
        unsigned long long t1 = fadd2(d2, d3);
        unsigned long long t2 = fadd2(d4, d5);
        unsigned long long t3 = fadd2(d6, d7);
        t0 = fadd2(t0, t1);
        t2 = fadd2(t2, t3);
        t0 = fadd2(t0, t2);

        float lo = __uint_as_float((unsigned)t0);
        float hi = __uint_as_float((unsigned)(t0 >> 32));
        float l1 = lo + hi;

        sum += __expf(-l1);
    }

    out[(size_t)b * OUTW + F_SZ + k] = sum;
}

// ---------------------------------------------------------------------------
extern "C" void kernel_launch(void* const* d_in, const int* in_sizes, int n_in,
                              void* d_out, int out_size) {
    const float* x = (const float*)d_in[0];
    const float* W = (const float*)d_in[1];
    float* out = (float*)d_out;

    dim3 gemm_grid((NCOL + 63) / 64, B_SZ / 64, KSPLIT);   // 13 x 8 x 4
    gemm_kernel<<<gemm_grid, 256>>>(x, W);

    copyx_kernel<<<512, 256>>>(x, out);

    dim3 pw_grid(B_SZ / 128, NK);                          // 4 x 50
    pairwise_kernel<<<pw_grid, 128>>>(out);
}

// round 3
// speedup vs baseline: 1.3964x; 1.3036x over previous
#include <cuda_runtime.h>

#define B_SZ   512
#define F_SZ   512
#define NK     50
#define DK     16
#define NCOL   (NK*DK)     // 800
#define OUTW   (F_SZ + NK) // 562
#define KSPLIT 8
#define KCHUNK (F_SZ / KSPLIT)   // 64
#define ACT_SZ (B_SZ * NCOL)

__device__ float g_act_part[KSPLIT * ACT_SZ];  // split-K partials
__device__ float g_act[ACT_SZ];                // reduced activations

// tile-pair map: 10 pairs (I<=J) over 4 row-tiles of 128
__device__ const int PAIR_I[10] = {0,0,0,0,1,1,1,2,2,3};
__device__ const int PAIR_J[10] = {0,1,2,3,1,2,3,2,3,3};

// ---------------------------------------------------------------------------
// GEMM split-K: act_part[kc][m][n] = sum_{k in chunk kc} x[m][k] * W[k][n]
// ---------------------------------------------------------------------------
__global__ __launch_bounds__(256) void gemm_kernel(const float* __restrict__ A,
                                                   const float* __restrict__ Bm) {
    __shared__ float As[16][64];
    __shared__ float Bs[16][64];

    const int tid = threadIdx.x;
    const int m0  = blockIdx.y * 64;
    const int n0  = blockIdx.x * 64;
    const int kc  = blockIdx.z;
    float* out = g_act_part + kc * ACT_SZ;

    const int ty = tid >> 4;
    const int tx = tid & 15;

    float acc[4][4] = {};

    const int kbeg = kc * KCHUNK;
    for (int k0 = kbeg; k0 < kbeg + KCHUNK; k0 += 16) {
        #pragma unroll
        for (int p = 0; p < 4; p++) {
            int e = tid + p * 256;
            int r = e >> 4, c = e & 15;
            As[c][r] = A[(m0 + r) * F_SZ + (k0 + c)];
        }
        #pragma unroll
        for (int p = 0; p < 4; p++) {
            int e = tid + p * 256;
            int r = e >> 6, c = e & 63;
            int n = n0 + c;
            Bs[r][c] = (n < NCOL) ? Bm[(k0 + r) * NCOL + n] : 0.0f;
        }
        __syncthreads();

        #pragma unroll
        for (int kk = 0; kk < 16; kk++) {
            float a[4], b[4];
            #pragma unroll
            for (int i = 0; i < 4; i++) a[i] = As[kk][ty * 4 + i];
            #pragma unroll
            for (int j = 0; j < 4; j++) b[j] = Bs[kk][tx * 4 + j];
            #pragma unroll
            for (int i = 0; i < 4; i++)
                #pragma unroll
                for (int j = 0; j < 4; j++)
                    acc[i][j] += a[i] * b[j];
        }
        __syncthreads();
    }

    #pragma unroll
    for (int i = 0; i < 4; i++) {
        int m = m0 + ty * 4 + i;
        #pragma unroll
        for (int j = 0; j < 4; j++) {
            int n = n0 + tx * 4 + j;
            if (n < NCOL) out[m * NCOL + n] = acc[i][j];
        }
    }
}

// ---------------------------------------------------------------------------
// Reduce the 8 split-K partials into g_act (float4 granularity)
// ---------------------------------------------------------------------------
__global__ __launch_bounds__(256) void reduce_act_kernel() {
    int i = blockIdx.x * 256 + threadIdx.x;     // float4 index, 102400 total
    const float4* P = (const float4*)g_act_part;
    const int STRIDE4 = ACT_SZ / 4;
    float4 r = P[i];
    #pragma unroll
    for (int p = 1; p < KSPLIT; p++) {
        float4 v = P[i + p * STRIDE4];
        r.x += v.x; r.y += v.y; r.z += v.z; r.w += v.w;
    }
    ((float4*)g_act)[i] = r;
}

// ---------------------------------------------------------------------------
// Copy x into out[:,0:512] and ZERO out[:,512:562] (pairwise atomics need 0)
// Each row = 281 float2 (562 floats); row base is 8B-aligned.
// ---------------------------------------------------------------------------
__global__ __launch_bounds__(256) void prep_out_kernel(const float* __restrict__ x,
                                                       float* __restrict__ out) {
    int idx = blockIdx.x * 256 + threadIdx.x;   // 512*281 = 143872 exactly
    int b = idx / 281, j = idx - b * 281;
    float2 v;
    if (j < 256) v = ((const float2*)(x + (size_t)b * F_SZ))[j];
    else         v = make_float2(0.0f, 0.0f);
    ((float2*)(out + (size_t)b * OUTW))[j] = v;
}

// ---------------------------------------------------------------------------
// Symmetric pairwise. grid = (10 tile-pairs, 50 k), block = 128.
// Off-diagonal tiles are computed once and contribute to both I-rows (rowAcc)
// and J-rows (butterfly-reduced colAcc). Merge via atomicAdd.
// ---------------------------------------------------------------------------
__global__ __launch_bounds__(128) void pairwise_kernel(float* __restrict__ out) {
    __shared__ float4 sI[128 * 4];        // 8 KB
    __shared__ float4 sJ[128 * 4];        // 8 KB
    __shared__ float  colpart[4 * 128];   // 2 KB

    const int k    = blockIdx.y;
    const int tid  = threadIdx.x;
    const int lane = tid & 31;
    const int w    = tid >> 5;
    const int I = PAIR_I[blockIdx.x];
    const int J = PAIR_J[blockIdx.x];

    // stage I and J tiles of act[:,k,:]
    for (int i = tid; i < 128 * 4; i += 128) {
        int r = i >> 2, j = i & 3;
        sI[i] = *((const float4*)(g_act + (I * 128 + r) * NCOL + k * DK) + j);
        sJ[i] = *((const float4*)(g_act + (J * 128 + r) * NCOL + k * DK) + j);
    }
    __syncthreads();

    const float4 a0 = sI[tid * 4 + 0];
    const float4 a1 = sI[tid * 4 + 1];
    const float4 a2 = sI[tid * 4 + 2];
    const float4 a3 = sI[tid * 4 + 3];

    float rowAcc = 0.0f;
    const int rowB = I * 128 + tid;
    float* fbase = out + F_SZ + k;

    if (I == J) {
        // diagonal: full 128x128 including self (exp(0)=1)
        #pragma unroll 4
        for (int b2 = 0; b2 < 128; b2++) {
            float4 v0 = sJ[b2 * 4 + 0];
            float4 v1 = sJ[b2 * 4 + 1];
            float4 v2 = sJ[b2 * 4 + 2];
            float4 v3 = sJ[b2 * 4 + 3];
            float p0 = fabsf(a0.x - v0.x) + fabsf(a0.y - v0.y)
                     + fabsf(a0.z - v0.z) + fabsf(a0.w - v0.w);
            float p1 = fabsf(a1.x - v1.x) + fabsf(a1.y - v1.y)
                     + fabsf(a1.z - v1.z) + fabsf(a1.w - v1.w);
            float p2 = fabsf(a2.x - v2.x) + fabsf(a2.y - v2.y)
                     + fabsf(a2.z - v2.z) + fabsf(a2.w - v2.w);
            float p3 = fabsf(a3.x - v3.x) + fabsf(a3.y - v3.y)
                     + fabsf(a3.z - v3.z) + fabsf(a3.w - v3.w);
            rowAcc += __expf(-((p0 + p1) + (p2 + p3)));
        }
        atomicAdd(fbase + (size_t)rowB * OUTW, rowAcc);
    } else {
        float colAcc[4] = {0.0f, 0.0f, 0.0f, 0.0f};
        #pragma unroll
        for (int c = 0; c < 4; c++) {
            #pragma unroll 4
            for (int s = 0; s < 32; s++) {
                int b2 = c * 32 + s;
                float4 v0 = sJ[b2 * 4 + 0];
                float4 v1 = sJ[b2 * 4 + 1];
                float4 v2 = sJ[b2 * 4 + 2];
                float4 v3 = sJ[b2 * 4 + 3];
                float p0 = fabsf(a0.x - v0.x) + fabsf(a0.y - v0.y)
                         + fabsf(a0.z - v0.z) + fabsf(a0.w - v0.w);
                float p1 = fabsf(a1.x - v1.x) + fabsf(a1.y - v1.y)
                         + fabsf(a1.z - v1.z) + fabsf(a1.w - v1.w);
                float p2 = fabsf(a2.x - v2.x) + fabsf(a2.y - v2.y)
                         + fabsf(a2.z - v2.z) + fabsf(a2.w - v2.w);
                float p3 = fabsf(a3.x - v3.x) + fabsf(a3.y - v3.y)
                         + fabsf(a3.z - v3.z) + fabsf(a3.w - v3.w);
                float e = __expf(-((p0 + p1) + (p2 + p3)));
                rowAcc += e;
                // butterfly all-reduce over the warp
                float tot = e;
                #pragma unroll
                for (int off = 16; off; off >>= 1)
                    tot += __shfl_xor_sync(0xFFFFFFFFu, tot, off);
                if (lane == s) colAcc[c] += tot;
            }
        }
        atomicAdd(fbase + (size_t)rowB * OUTW, rowAcc);

        // merge per-warp column partials -> one atomic per column
        #pragma unroll
        for (int c = 0; c < 4; c++)
            colpart[w * 128 + c * 32 + lane] = colAcc[c];
        __syncthreads();
        float csum = colpart[0 * 128 + tid] + colpart[1 * 128 + tid]
                   + colpart[2 * 128 + tid] + colpart[3 * 128 + tid];
        atomicAdd(fbase + (size_t)(J * 128 + tid) * OUTW, csum);
    }
}

// ---------------------------------------------------------------------------
extern "C" void kernel_launch(void* const* d_in, const int* in_sizes, int n_in,
                              void* d_out, int out_size) {
    const float* x = (const float*)d_in[0];
    const float* W = (const float*)d_in[1];
    float* out = (float*)d_out;

    dim3 gemm_grid((NCOL + 63) / 64, B_SZ / 64, KSPLIT);   // 13 x 8 x 8
    gemm_kernel<<<gemm_grid, 256>>>(x, W);

    reduce_act_kernel<<<ACT_SZ / 4 / 256, 256>>>();        // 400 blocks

    prep_out_kernel<<<562, 256>>>(x, out);                 // copy + zero

    dim3 pw_grid(10, NK);                                  // 10 x 50
    pairwise_kernel<<<pw_grid, 128>>>(out);
}

// round 5
// speedup vs baseline: 1.4342x; 1.0271x over previous
#include <cuda_runtime.h>

#define B_SZ   512
#define F_SZ   512
#define NK     50
#define DK     16
#define NCOL   (NK*DK)     // 800
#define OUTW   (F_SZ + NK) // 562
#define KSPLIT 8
#define KCHUNK (F_SZ / KSPLIT)   // 64
#define ACT_SZ (B_SZ * NCOL)

__device__ float g_act_part[KSPLIT * ACT_SZ];  // split-K partials
__device__ float g_act[ACT_SZ];                // reduced activations

// 20 pairwise block descriptors: (I row-tile, J col-tile, col-chunk)
// 0-7: diag (I==J) x 2 chunks;  8-19: off-diag (I<J) x 2 chunks
__constant__ int BP_I[20] = {0,0,1,1,2,2,3,3, 0,0,0,0,0,0,1,1,1,1,2,2};
__constant__ int BP_J[20] = {0,0,1,1,2,2,3,3, 1,1,2,2,3,3,2,2,3,3,3,3};
__constant__ int BP_C[20] = {0,1,0,1,0,1,0,1, 0,1,0,1,0,1,0,1,0,1,0,1};

// ---------------------------------------------------------------------------
// GEMM split-K: act_part[kc][m][n] = sum_{k in chunk kc} x[m][k] * W[k][n]
// ---------------------------------------------------------------------------
__global__ __launch_bounds__(256) void gemm_kernel(const float* __restrict__ A,
                                                   const float* __restrict__ Bm) {
    __shared__ float As[16][64];
    __shared__ float Bs[16][64];

    const int tid = threadIdx.x;
    const int m0  = blockIdx.y * 64;
    const int n0  = blockIdx.x * 64;
    const int kc  = blockIdx.z;
    float* out = g_act_part + kc * ACT_SZ;

    const int ty = tid >> 4;
    const int tx = tid & 15;

    float acc[4][4] = {};

    const int kbeg = kc * KCHUNK;
    for (int k0 = kbeg; k0 < kbeg + KCHUNK; k0 += 16) {
        #pragma unroll
        for (int p = 0; p < 4; p++) {
            int e = tid + p * 256;
            int r = e >> 4, c = e & 15;
            As[c][r] = A[(m0 + r) * F_SZ + (k0 + c)];
        }
        #pragma unroll
        for (int p = 0; p < 4; p++) {
            int e = tid + p * 256;
            int r = e >> 6, c = e & 63;
            int n = n0 + c;
            Bs[r][c] = (n < NCOL) ? Bm[(k0 + r) * NCOL + n] : 0.0f;
        }
        __syncthreads();

        #pragma unroll
        for (int kk = 0; kk < 16; kk++) {
            float a[4], b[4];
            #pragma unroll
            for (int i = 0; i < 4; i++) a[i] = As[kk][ty * 4 + i];
            #pragma unroll
            for (int j = 0; j < 4; j++) b[j] = Bs[kk][tx * 4 + j];
            #pragma unroll
            for (int i = 0; i < 4; i++)
                #pragma unroll
                for (int j = 0; j < 4; j++)
                    acc[i][j] += a[i] * b[j];
        }
        __syncthreads();
    }

    #pragma unroll
    for (int i = 0; i < 4; i++) {
        int m = m0 + ty * 4 + i;
        #pragma unroll
        for (int j = 0; j < 4; j++) {
            int n = n0 + tx * 4 + j;
            if (n < NCOL) out[m * NCOL + n] = acc[i][j];
        }
    }
}

// ---------------------------------------------------------------------------
// Reduce the 8 split-K partials into g_act
// ---------------------------------------------------------------------------
__global__ __launch_bounds__(256) void reduce_act_kernel() {
    int i = blockIdx.x * 256 + threadIdx.x;     // float4 index
    const float4* P = (const float4*)g_act_part;
    const int STRIDE4 = ACT_SZ / 4;
    float4 r = P[i];
    #pragma unroll
    for (int p = 1; p < KSPLIT; p++) {
        float4 v = P[i + p * STRIDE4];
        r.x += v.x; r.y += v.y; r.z += v.z; r.w += v.w;
    }
    ((float4*)g_act)[i] = r;
}

// ---------------------------------------------------------------------------
// Copy x into out[:,0:512] and ZERO out[:,512:562]
// ---------------------------------------------------------------------------
__global__ __launch_bounds__(256) void prep_out_kernel(const float* __restrict__ x,
                                                       float* __restrict__ out) {
    int idx = blockIdx.x * 256 + threadIdx.x;   // 512*281 = 143872 exactly
    int b = idx / 281, j = idx - b * 281;
    float2 v;
    if (j < 256) v = ((const float2*)(x + (size_t)b * F_SZ))[j];
    else         v = make_float2(0.0f, 0.0f);
    ((float2*)(out + (size_t)b * OUTW))[j] = v;
}

// ---------------------------------------------------------------------------
// Symmetric pairwise, col-chunked.
// grid = (20 block-descs, 50 k), block = 128 threads.
// Thread t owns row I*128+t (registers, from global). The 64-col J chunk is
// staged in 4KB smem (broadcast reads). Diag tiles: direct row sums only.
// Off-diag: row sums + butterfly column sums, both merged via atomicAdd.
// ---------------------------------------------------------------------------
__global__ __launch_bounds__(128) void pairwise_kernel(float* __restrict__ out) {
    __shared__ float4 sJ[64 * 4];       // 4 KB: 64 cols x 16 floats
    __shared__ float  colpart[4 * 64];  // 1 KB: per-warp column partials

    const int k    = blockIdx.y;
    const int tid  = threadIdx.x;
    const int lane = tid & 31;
    const int w    = tid >> 5;
    const int I  = BP_I[blockIdx.x];
    const int J  = BP_J[blockIdx.x];
    const int c0 = BP_C[blockIdx.x] * 64;   // column-chunk base within J tile

    // stage the 64-row J chunk of act[:,k,:]
    #pragma unroll
    for (int p = 0; p < 2; p++) {
        int i = tid + p * 128;
        int r = i >> 2, j = i & 3;
        sJ[i] = *((const float4*)(g_act + (J * 128 + c0 + r) * NCOL + k * DK) + j);
    }
    __syncthreads();

    // own row in registers
    const float4* rp = (const float4*)(g_act + (size_t)(I * 128 + tid) * NCOL + k * DK);
    const float4 a0 = rp[0], a1 = rp[1], a2 = rp[2], a3 = rp[3];

    float rowAcc = 0.0f;
    float* fbase = out + F_SZ + k;

    if (I == J) {
        // direct: 128 rows x 64 cols (self-term included when row==col)
        #pragma unroll 4
        for (int b2 = 0; b2 < 64; b2++) {
            float4 v0 = sJ[b2 * 4 + 0];
            float4 v1 = sJ[b2 * 4 + 1];
            float4 v2 = sJ[b2 * 4 + 2];
            float4 v3 = sJ[b2 * 4 + 3];
            float p0 = fabsf(a0.x - v0.x) + fabsf(a0.y - v0.y)
                     + fabsf(a0.z - v0.z) + fabsf(a0.w - v0.w);
            float p1 = fabsf(a1.x - v1.x) + fabsf(a1.y - v1.y)
                     + fabsf(a1.z - v1.z) + fabsf(a1.w - v1.w);
            float p2 = fabsf(a2.x - v2.x) + fabsf(a2.y - v2.y)
                     + fabsf(a2.z - v2.z) + fabsf(a2.w - v2.w);
            float p3 = fabsf(a3.x - v3.x) + fabsf(a3.y - v3.y)
                     + fabsf(a3.z - v3.z) + fabsf(a3.w - v3.w);
            rowAcc += __expf(-((p0 + p1) + (p2 + p3)));
        }
        atomicAdd(fbase + (size_t)(I * 128 + tid) * OUTW, rowAcc);
    } else {
        float colAcc[2] = {0.0f, 0.0f};
        #pragma unroll
        for (int c = 0; c < 2; c++) {
            #pragma unroll 4
            for (int s = 0; s < 32; s++) {
                int b2 = c * 32 + s;
                float4 v0 = sJ[b2 * 4 + 0];
                float4 v1 = sJ[b2 * 4 + 1];
                float4 v2 = sJ[b2 * 4 + 2];
                float4 v3 = sJ[b2 * 4 + 3];
                float p0 = fabsf(a0.x - v0.x) + fabsf(a0.y - v0.y)
                         + fabsf(a0.z - v0.z) + fabsf(a0.w - v0.w);
                float p1 = fabsf(a1.x - v1.x) + fabsf(a1.y - v1.y)
                         + fabsf(a1.z - v1.z) + fabsf(a1.w - v1.w);
                float p2 = fabsf(a2.x - v2.x) + fabsf(a2.y - v2.y)
                         + fabsf(a2.z - v2.z) + fabsf(a2.w - v2.w);
                float p3 = fabsf(a3.x - v3.x) + fabsf(a3.y - v3.y)
                         + fabsf(a3.z - v3.z) + fabsf(a3.w - v3.w);
                float e = __expf(-((p0 + p1) + (p2 + p3)));
                rowAcc += e;
                float tot = e;
                #pragma unroll
                for (int off = 16; off; off >>= 1)
                    tot += __shfl_xor_sync(0xFFFFFFFFu, tot, off);
                if (lane == s) colAcc[c] += tot;
            }
        }
        atomicAdd(fbase + (size_t)(I * 128 + tid) * OUTW, rowAcc);

        // cross-warp merge: one atomic per column
        colpart[w * 64 + 0 * 32 + lane] = colAcc[0];
        colpart[w * 64 + 1 * 32 + lane] = colAcc[1];
        __syncthreads();
        if (tid < 64) {
            float csum = colpart[0 * 64 + tid] + colpart[1 * 64 + tid]
                       + colpart[2 * 64 + tid] + colpart[3 * 64 + tid];
            atomicAdd(fbase + (size_t)(J * 128 + c0 + tid) * OUTW, csum);
        }
    }
}

// ---------------------------------------------------------------------------
extern "C" void kernel_launch(void* const* d_in, const int* in_sizes, int n_in,
                              void* d_out, int out_size) {
    const float* x = (const float*)d_in[0];
    const float* W = (const float*)d_in[1];
    float* out = (float*)d_out;

    dim3 gemm_grid((NCOL + 63) / 64, B_SZ / 64, KSPLIT);   // 13 x 8 x 8
    gemm_kernel<<<gemm_grid, 256>>>(x, W);

    reduce_act_kernel<<<ACT_SZ / 4 / 256, 256>>>();        // 400 blocks

    prep_out_kernel<<<562, 256>>>(x, out);                 // copy + zero

    dim3 pw_grid(20, NK);                                  // 20 x 50 = 1000
    pairwise_kernel<<<pw_grid, 128>>>(out);
}